// round 14
// baseline (speedup 1.0000x reference)
#include <cuda_runtime.h>
#include <cuda_fp16.h>
#include <cstdint>

#define NEXP 8
#define DIN  1024
#define DOUT 1024
#define NTOK 8192

#define BM 128
#define BN 128
#define BK 32
#define THREADS 256

#define ROWPITCH 80                      /* 32 fp16 = 64B data, padded to 80B */
#define A_TILE_B (128 * ROWPITCH)        /* 10240 */
#define STAGE_B  (2 * A_TILE_B)          /* 20480: A, B */
#define NSTAGE   4
#define SMEM_BYTES (NSTAGE * STAGE_B)    /* 81920 -> 2 CTAs/SM */
#define B_OFF    A_TILE_B

#define NTILES   4096                    /* 8 nt x 64 mt x 8 e */

// ---------------- scratch (device globals; no allocation) ----------------
__device__ int    g_cnt[NEXP];
__device__ int    g_tile[2];             // persistent tile counters (gemm1, gemm2)
__device__ int    g_tok[NEXP * NTOK];
__device__ float  g_wt [NEXP * NTOK];
__device__ __half g_x16[(size_t)NTOK * DIN];
__device__ __half g_h16[(size_t)NEXP * NTOK * DOUT];
__device__ __half g_W1T[(size_t)NEXP * DIN * DOUT];   // fp16, transposed [E][N][K]
__device__ __half g_W2T[(size_t)NEXP * DOUT * DOUT];

// ---------------- side stream + events (static init: pre-checkpoint) -----
static cudaStream_t g_s2;
static cudaEvent_t  g_evFork, g_evW1, g_evAux;
static struct StreamInit {
    StreamInit() {
        cudaStreamCreateWithFlags(&g_s2, cudaStreamNonBlocking);
        cudaEventCreateWithFlags(&g_evFork, cudaEventDisableTiming);
        cudaEventCreateWithFlags(&g_evW1,   cudaEventDisableTiming);
        cudaEventCreateWithFlags(&g_evAux,  cudaEventDisableTiming);
    }
} g_streamInit;

// ---------------- helpers ----------------
__device__ __forceinline__ uint32_t smem_u32(const void* p) {
    uint32_t a;
    asm("{ .reg .u64 t; cvta.to.shared.u64 t, %1; cvt.u32.u64 %0, t; }" : "=r"(a) : "l"(p));
    return a;
}
__device__ __forceinline__ void cp_async16(uint32_t dst, const void* src) {
    asm volatile("cp.async.cg.shared.global [%0], [%1], 16;" :: "r"(dst), "l"(src) : "memory");
}
#define CP_COMMIT() asm volatile("cp.async.commit_group;" ::: "memory")
#define CP_WAIT2()  asm volatile("cp.async.wait_group 2;" ::: "memory")
#define CP_WAIT0()  asm volatile("cp.async.wait_group 0;" ::: "memory")

__device__ __forceinline__ void mma_f16(float* d, const uint32_t* a, const uint32_t* b) {
    asm volatile(
        "mma.sync.aligned.m16n8k16.row.col.f32.f16.f16.f32 "
        "{%0,%1,%2,%3},{%4,%5,%6,%7},{%8,%9},{%0,%1,%2,%3};"
        : "+f"(d[0]), "+f"(d[1]), "+f"(d[2]), "+f"(d[3])
        : "r"(a[0]), "r"(a[1]), "r"(a[2]), "r"(a[3]), "r"(b[0]), "r"(b[1]));
}
__device__ __forceinline__ void ldmx4(uint32_t* r, uint32_t addr) {
    asm volatile("ldmatrix.sync.aligned.m8n8.x4.shared.b16 {%0,%1,%2,%3}, [%4];"
                 : "=r"(r[0]), "=r"(r[1]), "=r"(r[2]), "=r"(r[3]) : "r"(addr));
}
__device__ __forceinline__ void red_add_v2(float* addr, float v0, float v1) {
    asm volatile("red.global.add.v2.f32 [%0], {%1, %2};"
                 :: "l"(addr), "f"(v0), "f"(v1) : "memory");
}

// ---------------------------------------------------------------------------
__global__ void zero_cnt_kernel() {
    if (threadIdx.x < NEXP) g_cnt[threadIdx.x] = 0;
    if (threadIdx.x < 2)    g_tile[threadIdx.x] = 0;
}
__global__ void zero_out_kernel(float* __restrict__ out) {
    int i = blockIdx.x * blockDim.x + threadIdx.x;
    ((float4*)out)[i] = make_float4(0.f, 0.f, 0.f, 0.f);
}

// ---------------------------------------------------------------------------
// Gating + x->fp16 conversion (proven rolled form).
// ---------------------------------------------------------------------------
__global__ void gate_convert_kernel(const float* __restrict__ x,
                                    const float* __restrict__ Wg,
                                    const float* __restrict__ bg) {
    int warp = (blockIdx.x * blockDim.x + threadIdx.x) >> 5;
    int lane = threadIdx.x & 31;
    if (warp >= NTOK) return;
    const float* xr = x + (size_t)warp * DIN;
    __half* xo = g_x16 + (size_t)warp * DIN;
    float acc[NEXP];
#pragma unroll
    for (int e = 0; e < NEXP; e++) acc[e] = 0.f;
    for (int kk = 0; kk < DIN / 32; kk++) {
        int k = kk * 32 + lane;
        float xv = xr[k];
        xo[k] = __float2half(xv);
        const float* wr = Wg + k * NEXP;
#pragma unroll
        for (int e = 0; e < NEXP; e++) acc[e] += xv * wr[e];
    }
#pragma unroll
    for (int e = 0; e < NEXP; e++)
#pragma unroll
        for (int o = 16; o > 0; o >>= 1)
            acc[e] += __shfl_xor_sync(0xffffffffu, acc[e], o);
    if (lane == 0) {
        float m = -1e30f;
#pragma unroll
        for (int e = 0; e < NEXP; e++) { acc[e] += bg[e]; m = fmaxf(m, acc[e]); }
        float s = 0.f;
#pragma unroll
        for (int e = 0; e < NEXP; e++) { acc[e] = expf(acc[e] - m); s += acc[e]; }
        float inv = 1.f / s;
        int e0 = 0, e1 = -1;
        float v0 = acc[0], v1 = -1.f;
#pragma unroll
        for (int e = 1; e < NEXP; e++) {
            float v = acc[e];
            if (v > v0)      { v1 = v0; e1 = e0; v0 = v; e0 = e; }
            else if (v > v1) { v1 = v;  e1 = e; }
        }
        int p0 = atomicAdd(&g_cnt[e0], 1);
        g_tok[e0 * NTOK + p0] = warp;  g_wt[e0 * NTOK + p0] = v0 * inv;
        int p1 = atomicAdd(&g_cnt[e1], 1);
        g_tok[e1 * NTOK + p1] = warp;  g_wt[e1 * NTOK + p1] = v1 * inv;
    }
}

// ---------------------------------------------------------------------------
__global__ void transpose_half_kernel(const float* __restrict__ W,
                                      __half* __restrict__ WT) {
    __shared__ float t[32][33];
    int e = blockIdx.z;
    const float* Ws = W + ((size_t)e << 20);
    int x0 = blockIdx.x * 32, y0 = blockIdx.y * 32;
    int tx = threadIdx.x, ty = threadIdx.y;
#pragma unroll
    for (int i = 0; i < 32; i += 8)
        t[ty + i][tx] = Ws[(size_t)(y0 + ty + i) * 1024 + x0 + tx];
    __syncthreads();
#pragma unroll
    for (int i = 0; i < 32; i += 8) {
        size_t o = ((size_t)e << 20) + (size_t)(x0 + ty + i) * 1024 + y0 + tx;
        WT[o] = __float2half(t[tx][ty + i]);
    }
}

// ---------------------------------------------------------------------------
// Persistent fp16 mma.sync GEMM. Tile ids come from a global atomic counter,
// fetched by tid 0 ONLY and broadcast through shared memory (the R13 crash
// was every thread fetching its own id -> divergent __syncthreads).
// Loop discipline per iteration:
//   top sync (all consumed t) -> tid0 prefetches s_next -> tile body
//   -> bottom sync (publish) -> t = s_next
// ---------------------------------------------------------------------------
template <bool G2>
__global__ __launch_bounds__(THREADS, 2)
void moe_mma_kernel(const __half* __restrict__ Wt,
                    const float* __restrict__ bias,
                    float* __restrict__ outp) {
    extern __shared__ char smem[];
    __shared__ int   s_tok[BM];
    __shared__ float s_wt[BM];
    __shared__ float s_bias[BN];
    __shared__ int   s_next;

    const int tid  = threadIdx.x;
    const int wid  = tid >> 5;
    const int lane = tid & 31;
    const uint32_t sb = smem_u32(smem);

    const int r0 = tid >> 2;             // 0..63
    const int ch = tid & 3;              // 16B chunk in 64B row
    const uint32_t sA = sb + r0 * ROWPITCH + ch * 16;
    const uint32_t sB = sb + B_OFF + r0 * ROWPITCH + ch * 16;

    const int wm = wid >> 2;
    const int wn = wid & 3;
    const int aRow  = wm * 64 + (lane & 7) + ((lane >> 3) & 1) * 8;
    const int aKoff = ((lane >> 4) & 1) * 16;
    const int bRow  = wn * 32 + (lane & 7) + ((lane >> 4) & 1) * 8;
    const int bKoff = ((lane >> 3) & 1) * 16;
    const int lr = lane >> 2;
    const int lc = (lane & 3) * 2;

    int* ctr = &g_tile[G2 ? 1 : 0];

    if (tid == 0) s_next = atomicAdd(ctr, 1);
    __syncthreads();
    int t = s_next;

    while (t < NTILES) {
        __syncthreads();                 // all threads have consumed t
        if (tid == 0) s_next = atomicAdd(ctr, 1);   // prefetch next tile id

        const int e   = t & 7;
        const int cnt = g_cnt[e];
        const int m0  = ((t >> 3) & 63) * BM;
        const int n0  = (t >> 9) * BN;

        if (m0 < cnt) {
            if (tid < BM) {
                int ok = (m0 + tid) < cnt;
                s_tok[tid] = ok ? g_tok[e * NTOK + m0 + tid] : 0;
                s_wt[tid]  = ok ? g_wt[e * NTOK + m0 + tid] : 0.f;
                s_bias[tid] = bias[e * 1024 + n0 + tid];
            }
            __syncthreads();

            const __half* pA0;
            const __half* pA1;
            if (G2) {
                pA0 = g_h16 + ((size_t)e * NTOK + m0 + r0) * 1024 + ch * 8;
                pA1 = pA0 + (size_t)64 * 1024;
            } else {
                pA0 = g_x16 + (size_t)s_tok[r0] * 1024 + ch * 8;
                pA1 = g_x16 + (size_t)s_tok[r0 + 64] * 1024 + ch * 8;
            }
            const __half* pB = Wt + (((size_t)e << 10) + n0 + r0) * 1024 + ch * 8;

            auto issue = [&](int s, int c) {
                const uint32_t so = (uint32_t)(s * STAGE_B);
                const size_t ko = (size_t)c * BK;
                cp_async16(sA + so,                 pA0 + ko);
                cp_async16(sA + so + 64 * ROWPITCH, pA1 + ko);
                cp_async16(sB + so,                 pB + ko);
                cp_async16(sB + so + 64 * ROWPITCH, pB + (size_t)64 * 1024 + ko);
            };

            float ac[4][4][4];
#pragma unroll
            for (int a = 0; a < 4; a++)
#pragma unroll
                for (int b = 0; b < 4; b++)
#pragma unroll
                    for (int c = 0; c < 4; c++) ac[a][b][c] = 0.f;

            issue(0, 0); CP_COMMIT();
            issue(1, 1); CP_COMMIT();
            issue(2, 2); CP_COMMIT();

            const int NITER = DIN / BK;          // 32
            for (int c = 0; c < NITER; c++) {
                const int s = c & 3;
                CP_WAIT2();
                __syncthreads();
                if (c + 3 < NITER) issue((c + 3) & 3, c + 3);
                CP_COMMIT();

                const uint32_t stg = sb + s * STAGE_B;
                const uint32_t At = stg;
                const uint32_t Bt = stg + B_OFF;

#pragma unroll
                for (int ks = 0; ks < 2; ks++) {
                    const uint32_t aoff = (uint32_t)(aRow * ROWPITCH + ks * 32 + aKoff);
                    const uint32_t boff = (uint32_t)(bRow * ROWPITCH + ks * 32 + bKoff);
                    uint32_t af[4][4], bf[2][4];
#pragma unroll
                    for (int mf = 0; mf < 4; mf++)
                        ldmx4(af[mf], At + aoff + mf * 16 * ROWPITCH);
#pragma unroll
                    for (int np = 0; np < 2; np++)
                        ldmx4(bf[np], Bt + boff + np * 16 * ROWPITCH);
#pragma unroll
                    for (int mf = 0; mf < 4; mf++)
#pragma unroll
                        for (int nf = 0; nf < 4; nf++)
                            mma_f16(ac[mf][nf], af[mf], &bf[nf >> 1][(nf & 1) * 2]);
                }
            }
            CP_WAIT0();   // drain async groups before buffers are reused next tile

            // ---- epilogue ----
#pragma unroll
            for (int mf = 0; mf < 4; mf++) {
#pragma unroll
                for (int nf = 0; nf < 4; nf++) {
                    const float* d = ac[mf][nf];
                    int col_l = wn * 32 + nf * 8 + lc;
                    int colg  = n0 + col_l;
                    float bb0 = s_bias[col_l], bb1 = s_bias[col_l + 1];
#pragma unroll
                    for (int half = 0; half < 2; half++) {
                        int row = wm * 64 + mf * 16 + lr + half * 8;
                        if (m0 + row >= cnt) continue;
                        float v0 = d[half * 2]     + bb0;
                        float v1 = d[half * 2 + 1] + bb1;
                        if (!G2) {
                            v0 = fmaxf(v0, 0.f);  v1 = fmaxf(v1, 0.f);
                            size_t base = ((size_t)e * NTOK + m0 + row) * 1024 + colg;
                            *(__half2*)(g_h16 + base) =
                                __halves2half2(__float2half(v0), __float2half(v1));
                        } else {
                            float w = s_wt[row];
                            float* o = outp + (size_t)s_tok[row] * 1024 + colg;
                            red_add_v2(o, w * v0, w * v1);
                        }
                    }
                }
            }
        }
        __syncthreads();                 // s_next published; tile work done
        t = s_next;
    }
}

// ---------------------------------------------------------------------------
// Two-stream schedule (graph-capturable fork/join):
//   main: zero_cnt -> gate_convert -> [wait W1T] gemm1 -> [wait aux] gemm2
//   s2:   [wait fork] transpose(W1) -> transpose(W2) -> zero_out
// ---------------------------------------------------------------------------
extern "C" void kernel_launch(void* const* d_in, const int* in_sizes, int n_in,
                              void* d_out, int out_size) {
    const float* x  = (const float*)d_in[0];
    const float* W1 = (const float*)d_in[1];
    const float* b1 = (const float*)d_in[2];
    const float* W2 = (const float*)d_in[3];
    const float* b2 = (const float*)d_in[4];
    const float* Wg = (const float*)d_in[5];
    const float* bg = (const float*)d_in[6];
    float* out = (float*)d_out;

    cudaFuncSetAttribute(moe_mma_kernel<false>,
                         cudaFuncAttributeMaxDynamicSharedMemorySize, SMEM_BYTES);
    cudaFuncSetAttribute(moe_mma_kernel<true>,
                         cudaFuncAttributeMaxDynamicSharedMemorySize, SMEM_BYTES);

    int nsm = 148;
    cudaDeviceGetAttribute(&nsm, cudaDevAttrMultiProcessorCount, 0);
    const int ncta = 2 * nsm;

    __half *w1t, *w2t;
    cudaGetSymbolAddress((void**)&w1t, g_W1T);
    cudaGetSymbolAddress((void**)&w2t, g_W2T);

    cudaEventRecord(g_evFork, 0);
    cudaStreamWaitEvent(g_s2, g_evFork, 0);

    dim3 tg(32, 32, 8);
    transpose_half_kernel<<<tg, dim3(32, 8), 0, g_s2>>>(W1, w1t);
    cudaEventRecord(g_evW1, g_s2);
    transpose_half_kernel<<<tg, dim3(32, 8), 0, g_s2>>>(W2, w2t);
    zero_out_kernel<<<(NTOK * DOUT) / 4 / 256, 256, 0, g_s2>>>(out);
    cudaEventRecord(g_evAux, g_s2);

    zero_cnt_kernel<<<1, 32>>>();
    gate_convert_kernel<<<(NTOK * 32) / 256, 256>>>(x, Wg, bg);

    cudaStreamWaitEvent(0, g_evW1, 0);
    moe_mma_kernel<false><<<ncta, THREADS, SMEM_BYTES>>>(w1t, b1, nullptr);

    cudaStreamWaitEvent(0, g_evAux, 0);
    moe_mma_kernel<true><<<ncta, THREADS, SMEM_BYTES>>>(w2t, b2, out);
}

// round 15
// speedup vs baseline: 1.1587x; 1.1587x over previous
#include <cuda_runtime.h>
#include <cuda_fp16.h>
#include <cstdint>

#define NEXP 8
#define DIN  1024
#define DOUT 1024
#define NTOK 8192

#define BM 128
#define BN 128
#define BK 32
#define THREADS 256

#define ROWPITCH 80                      /* 32 fp16 = 64B data, padded to 80B */
#define A_TILE_B (128 * ROWPITCH)        /* 10240 */
#define STAGE_B  (2 * A_TILE_B)          /* 20480: A, B */
#define NSTAGE   4
#define SMEM_BYTES (NSTAGE * STAGE_B)    /* 81920 -> 2 CTAs/SM */
#define B_OFF    A_TILE_B

// ---------------- scratch (device globals; no allocation) ----------------
__device__ int    g_cnt[NEXP];
__device__ int    g_tok[NEXP * NTOK];
__device__ float  g_wt [NEXP * NTOK];
__device__ __half g_x16[(size_t)NTOK * DIN];
__device__ __half g_h16[(size_t)NEXP * NTOK * DOUT];
__device__ __half g_W1T[(size_t)NEXP * DIN * DOUT];   // fp16, transposed [E][N][K]
__device__ __half g_W2T[(size_t)NEXP * DOUT * DOUT];

// ---------------- side stream + events (static init: pre-checkpoint) -----
static cudaStream_t g_s2;
static cudaEvent_t  g_evFork, g_evW1, g_evAux;
static struct StreamInit {
    StreamInit() {
        cudaStreamCreateWithFlags(&g_s2, cudaStreamNonBlocking);
        cudaEventCreateWithFlags(&g_evFork, cudaEventDisableTiming);
        cudaEventCreateWithFlags(&g_evW1,   cudaEventDisableTiming);
        cudaEventCreateWithFlags(&g_evAux,  cudaEventDisableTiming);
    }
} g_streamInit;

// ---------------- helpers ----------------
__device__ __forceinline__ uint32_t smem_u32(const void* p) {
    uint32_t a;
    asm("{ .reg .u64 t; cvta.to.shared.u64 t, %1; cvt.u32.u64 %0, t; }" : "=r"(a) : "l"(p));
    return a;
}
__device__ __forceinline__ void cp_async16(uint32_t dst, const void* src) {
    asm volatile("cp.async.cg.shared.global [%0], [%1], 16;" :: "r"(dst), "l"(src) : "memory");
}
#define CP_COMMIT() asm volatile("cp.async.commit_group;" ::: "memory")
#define CP_WAIT2()  asm volatile("cp.async.wait_group 2;" ::: "memory")

__device__ __forceinline__ void mma_f16(float* d, const uint32_t* a, const uint32_t* b) {
    asm volatile(
        "mma.sync.aligned.m16n8k16.row.col.f32.f16.f16.f32 "
        "{%0,%1,%2,%3},{%4,%5,%6,%7},{%8,%9},{%0,%1,%2,%3};"
        : "+f"(d[0]), "+f"(d[1]), "+f"(d[2]), "+f"(d[3])
        : "r"(a[0]), "r"(a[1]), "r"(a[2]), "r"(a[3]), "r"(b[0]), "r"(b[1]));
}
__device__ __forceinline__ void ldmx4(uint32_t* r, uint32_t addr) {
    asm volatile("ldmatrix.sync.aligned.m8n8.x4.shared.b16 {%0,%1,%2,%3}, [%4];"
                 : "=r"(r[0]), "=r"(r[1]), "=r"(r[2]), "=r"(r[3]) : "r"(addr));
}
__device__ __forceinline__ void red_add_v2(float* addr, float v0, float v1) {
    asm volatile("red.global.add.v2.f32 [%0], {%1, %2};"
                 :: "l"(addr), "f"(v0), "f"(v1) : "memory");
}

// ---------------------------------------------------------------------------
__global__ void zero_cnt_kernel() {
    if (threadIdx.x < NEXP) g_cnt[threadIdx.x] = 0;
}
__global__ void zero_out_kernel(float* __restrict__ out) {
    int i = blockIdx.x * blockDim.x + threadIdx.x;
    ((float4*)out)[i] = make_float4(0.f, 0.f, 0.f, 0.f);
}

// ---------------------------------------------------------------------------
// Gating + x->fp16 conversion (proven rolled form).
// ---------------------------------------------------------------------------
__global__ void gate_convert_kernel(const float* __restrict__ x,
                                    const float* __restrict__ Wg,
                                    const float* __restrict__ bg) {
    int warp = (blockIdx.x * blockDim.x + threadIdx.x) >> 5;
    int lane = threadIdx.x & 31;
    if (warp >= NTOK) return;
    const float* xr = x + (size_t)warp * DIN;
    __half* xo = g_x16 + (size_t)warp * DIN;
    float acc[NEXP];
#pragma unroll
    for (int e = 0; e < NEXP; e++) acc[e] = 0.f;
    for (int kk = 0; kk < DIN / 32; kk++) {
        int k = kk * 32 + lane;
        float xv = xr[k];
        xo[k] = __float2half(xv);
        const float* wr = Wg + k * NEXP;
#pragma unroll
        for (int e = 0; e < NEXP; e++) acc[e] += xv * wr[e];
    }
#pragma unroll
    for (int e = 0; e < NEXP; e++)
#pragma unroll
        for (int o = 16; o > 0; o >>= 1)
            acc[e] += __shfl_xor_sync(0xffffffffu, acc[e], o);
    if (lane == 0) {
        float m = -1e30f;
#pragma unroll
        for (int e = 0; e < NEXP; e++) { acc[e] += bg[e]; m = fmaxf(m, acc[e]); }
        float s = 0.f;
#pragma unroll
        for (int e = 0; e < NEXP; e++) { acc[e] = expf(acc[e] - m); s += acc[e]; }
        float inv = 1.f / s;
        int e0 = 0, e1 = -1;
        float v0 = acc[0], v1 = -1.f;
#pragma unroll
        for (int e = 1; e < NEXP; e++) {
            float v = acc[e];
            if (v > v0)      { v1 = v0; e1 = e0; v0 = v; e0 = e; }
            else if (v > v1) { v1 = v;  e1 = e; }
        }
        int p0 = atomicAdd(&g_cnt[e0], 1);
        g_tok[e0 * NTOK + p0] = warp;  g_wt[e0 * NTOK + p0] = v0 * inv;
        int p1 = atomicAdd(&g_cnt[e1], 1);
        g_tok[e1 * NTOK + p1] = warp;  g_wt[e1 * NTOK + p1] = v1 * inv;
    }
}

// ---------------------------------------------------------------------------
__global__ void transpose_half_kernel(const float* __restrict__ W,
                                      __half* __restrict__ WT) {
    __shared__ float t[32][33];
    int e = blockIdx.z;
    const float* Ws = W + ((size_t)e << 20);
    int x0 = blockIdx.x * 32, y0 = blockIdx.y * 32;
    int tx = threadIdx.x, ty = threadIdx.y;
#pragma unroll
    for (int i = 0; i < 32; i += 8)
        t[ty + i][tx] = Ws[(size_t)(y0 + ty + i) * 1024 + x0 + tx];
    __syncthreads();
#pragma unroll
    for (int i = 0; i < 32; i += 8) {
        size_t o = ((size_t)e << 20) + (size_t)(x0 + ty + i) * 1024 + y0 + tx;
        WT[o] = __float2half(t[tx][ty + i]);
    }
}

// ---------------------------------------------------------------------------
// fp16 single-term mma.sync GEMM: 128x128x32 tiles, 4-stage cp.async,
// 2 CTAs/SM. 8 warps = 2(M) x 4(N), warp tile 64x32.
// Static grid (8,64,8), early-exit on empty m-tiles (beats dynamic
// scheduling here: R14 measured the persistent variant 47us slower).
// ---------------------------------------------------------------------------
template <bool G2>
__global__ __launch_bounds__(THREADS, 2)
void moe_mma_kernel(const __half* __restrict__ Wt,
                    const float* __restrict__ bias,
                    float* __restrict__ outp) {
    extern __shared__ char smem[];
    __shared__ int   s_tok[BM];
    __shared__ float s_wt[BM];
    __shared__ float s_bias[BN];

    const int e   = blockIdx.z;
    const int cnt = g_cnt[e];
    const int m0  = blockIdx.y * BM;
    if (m0 >= cnt) return;
    const int n0  = blockIdx.x * BN;

    const int tid  = threadIdx.x;
    const int wid  = tid >> 5;
    const int lane = tid & 31;

    if (tid < BM) {
        int ok = (m0 + tid) < cnt;
        s_tok[tid] = ok ? g_tok[e * NTOK + m0 + tid] : 0;
        if (G2) s_wt[tid] = ok ? g_wt[e * NTOK + m0 + tid] : 0.f;
        s_bias[tid] = bias[e * 1024 + n0 + tid];
    }
    __syncthreads();

    // ---- cp.async geometry: 4 ops/thread/iter ----
    const uint32_t sb = smem_u32(smem);
    const int r0 = tid >> 2;             // 0..63
    const int ch = tid & 3;              // 16B chunk in 64B row

    const __half* pA0;
    const __half* pA1;
    if (G2) {
        pA0 = g_h16 + ((size_t)e * NTOK + m0 + r0) * 1024 + ch * 8;
        pA1 = pA0 + (size_t)64 * 1024;
    } else {
        pA0 = g_x16 + (size_t)s_tok[r0] * 1024 + ch * 8;
        pA1 = g_x16 + (size_t)s_tok[r0 + 64] * 1024 + ch * 8;
    }
    const __half* pB = Wt + (((size_t)e << 10) + n0 + r0) * 1024 + ch * 8;

    const uint32_t sA = sb + r0 * ROWPITCH + ch * 16;
    const uint32_t sB = sb + B_OFF + r0 * ROWPITCH + ch * 16;

    auto issue = [&](int s, int c) {
        const uint32_t so = (uint32_t)(s * STAGE_B);
        const size_t ko = (size_t)c * BK;
        cp_async16(sA + so,                 pA0 + ko);
        cp_async16(sA + so + 64 * ROWPITCH, pA1 + ko);
        cp_async16(sB + so,                 pB + ko);
        cp_async16(sB + so + 64 * ROWPITCH, pB + (size_t)64 * 1024 + ko);
    };

    float ac[4][4][4];
#pragma unroll
    for (int a = 0; a < 4; a++)
#pragma unroll
        for (int b = 0; b < 4; b++)
#pragma unroll
            for (int c = 0; c < 4; c++) ac[a][b][c] = 0.f;

    issue(0, 0); CP_COMMIT();
    issue(1, 1); CP_COMMIT();
    issue(2, 2); CP_COMMIT();

    const int wm = wid >> 2;             // 0..1 -> m offset 64*wm
    const int wn = wid & 3;              // 0..3 -> n offset 32*wn

    const int aRow  = wm * 64 + (lane & 7) + ((lane >> 3) & 1) * 8;
    const int aKoff = ((lane >> 4) & 1) * 16;
    const int bRow  = wn * 32 + (lane & 7) + ((lane >> 4) & 1) * 8;
    const int bKoff = ((lane >> 3) & 1) * 16;

    const int NITER = DIN / BK;          // 32
    for (int c = 0; c < NITER; c++) {
        const int s = c & 3;
        CP_WAIT2();
        __syncthreads();
        if (c + 3 < NITER) issue((c + 3) & 3, c + 3);
        CP_COMMIT();

        const uint32_t stg = sb + s * STAGE_B;
        const uint32_t At = stg;
        const uint32_t Bt = stg + B_OFF;

#pragma unroll
        for (int ks = 0; ks < 2; ks++) {
            const uint32_t aoff = (uint32_t)(aRow * ROWPITCH + ks * 32 + aKoff);
            const uint32_t boff = (uint32_t)(bRow * ROWPITCH + ks * 32 + bKoff);
            uint32_t af[4][4], bf[2][4];
#pragma unroll
            for (int mf = 0; mf < 4; mf++)
                ldmx4(af[mf], At + aoff + mf * 16 * ROWPITCH);
#pragma unroll
            for (int np = 0; np < 2; np++)
                ldmx4(bf[np], Bt + boff + np * 16 * ROWPITCH);
#pragma unroll
            for (int mf = 0; mf < 4; mf++)
#pragma unroll
                for (int nf = 0; nf < 4; nf++)
                    mma_f16(ac[mf][nf], af[mf], &bf[nf >> 1][(nf & 1) * 2]);
        }
    }

    // ---- epilogue: direct from registers (quads cover full 32B sectors) ----
    const int lr = lane >> 2;
    const int lc = (lane & 3) * 2;
#pragma unroll
    for (int mf = 0; mf < 4; mf++) {
#pragma unroll
        for (int nf = 0; nf < 4; nf++) {
            const float* d = ac[mf][nf];
            int col_l = wn * 32 + nf * 8 + lc;
            int colg  = n0 + col_l;
            float bb0 = s_bias[col_l], bb1 = s_bias[col_l + 1];
#pragma unroll
            for (int half = 0; half < 2; half++) {
                int row = wm * 64 + mf * 16 + lr + half * 8;  // local slot
                if (m0 + row >= cnt) continue;
                float v0 = d[half * 2]     + bb0;
                float v1 = d[half * 2 + 1] + bb1;
                if (!G2) {
                    v0 = fmaxf(v0, 0.f);  v1 = fmaxf(v1, 0.f);
                    size_t base = ((size_t)e * NTOK + m0 + row) * 1024 + colg;
                    *(__half2*)(g_h16 + base) =
                        __halves2half2(__float2half(v0), __float2half(v1));
                } else {
                    float w = s_wt[row];
                    float* o = outp + (size_t)s_tok[row] * 1024 + colg;
                    red_add_v2(o, w * v0, w * v1);
                }
            }
        }
    }
}

// ---------------------------------------------------------------------------
// Two-stream schedule (graph-capturable fork/join):
//   main: zero_cnt -> gate_convert -> [wait W1T] gemm1 -> [wait aux] gemm2
//   s2:   [wait fork] transpose(W1) -> transpose(W2) -> zero_out
// ---------------------------------------------------------------------------
extern "C" void kernel_launch(void* const* d_in, const int* in_sizes, int n_in,
                              void* d_out, int out_size) {
    const float* x  = (const float*)d_in[0];
    const float* W1 = (const float*)d_in[1];
    const float* b1 = (const float*)d_in[2];
    const float* W2 = (const float*)d_in[3];
    const float* b2 = (const float*)d_in[4];
    const float* Wg = (const float*)d_in[5];
    const float* bg = (const float*)d_in[6];
    float* out = (float*)d_out;

    cudaFuncSetAttribute(moe_mma_kernel<false>,
                         cudaFuncAttributeMaxDynamicSharedMemorySize, SMEM_BYTES);
    cudaFuncSetAttribute(moe_mma_kernel<true>,
                         cudaFuncAttributeMaxDynamicSharedMemorySize, SMEM_BYTES);

    __half *w1t, *w2t;
    cudaGetSymbolAddress((void**)&w1t, g_W1T);
    cudaGetSymbolAddress((void**)&w2t, g_W2T);

    cudaEventRecord(g_evFork, 0);
    cudaStreamWaitEvent(g_s2, g_evFork, 0);

    dim3 tg(32, 32, 8);
    transpose_half_kernel<<<tg, dim3(32, 8), 0, g_s2>>>(W1, w1t);
    cudaEventRecord(g_evW1, g_s2);
    transpose_half_kernel<<<tg, dim3(32, 8), 0, g_s2>>>(W2, w2t);
    zero_out_kernel<<<(NTOK * DOUT) / 4 / 256, 256, 0, g_s2>>>(out);
    cudaEventRecord(g_evAux, g_s2);

    zero_cnt_kernel<<<1, 32>>>();
    gate_convert_kernel<<<(NTOK * 32) / 256, 256>>>(x, Wg, bg);

    cudaStreamWaitEvent(0, g_evW1, 0);
    dim3 grid(DOUT / BN, NTOK / BM, NEXP);
    moe_mma_kernel<false><<<grid, THREADS, SMEM_BYTES>>>(w1t, b1, nullptr);

    cudaStreamWaitEvent(0, g_evAux, 0);
    moe_mma_kernel<true><<<grid, THREADS, SMEM_BYTES>>>(w2t, b2, out);
}